// round 14
// baseline (speedup 1.0000x reference)
#include <cuda_runtime.h>
#include <math.h>

#define BB 64
#define SS 512
#define HH 768
#define LL 9
#define NTOK (BB*SS)
#define TPW 8                // tokens per consumer warp
#define TOKPB 32             // tokens per block
#define NLP 5                // label pairs (9 labels + 1 zero pad)
#define NST 6                // ring slots
#define STAGE_K 64           // k-floats per stage
#define STAGE_F (TOKPB*STAGE_K)  // 2048 floats = 8KB
#define NITER (HH/STAGE_K)   // 12 stages

typedef unsigned long long u64;

__device__ __forceinline__ u64 pack2(float lo, float hi) {
    u64 r; asm("mov.b64 %0, {%1, %2};" : "=l"(r) : "f"(lo), "f"(hi)); return r;
}
__device__ __forceinline__ u64 dup2(float v) {
    u64 r; asm("mov.b64 %0, {%1, %1};" : "=l"(r) : "f"(v)); return r;
}
__device__ __forceinline__ void unpack2(u64 v, float &lo, float &hi) {
    asm("mov.b64 {%0, %1}, %2;" : "=f"(lo), "=f"(hi) : "l"(v));
}
__device__ __forceinline__ void ffma2(u64 &d, u64 a, u64 b) {
    asm("fma.rn.f32x2 %0, %1, %2, %0;" : "+l"(d) : "l"(a), "l"(b));
}
__device__ __forceinline__ u64 fadd2(u64 a, u64 b) {
    u64 r; asm("add.rn.f32x2 %0, %1, %2;" : "=l"(r) : "l"(a), "l"(b)); return r;
}
__device__ __forceinline__ void cp_async16(unsigned saddr, const void* gptr) {
    asm volatile("cp.async.cg.shared.global [%0], [%1], 16;" :: "r"(saddr), "l"(gptr));
}
__device__ __forceinline__ void cp_commit() { asm volatile("cp.async.commit_group;"); }
__device__ __forceinline__ void cp_wait2()  { asm volatile("cp.async.wait_group 2;"); }
__device__ __forceinline__ void mbar_init(unsigned a, unsigned cnt) {
    asm volatile("mbarrier.init.shared.b64 [%0], %1;" :: "r"(a), "r"(cnt) : "memory");
}
__device__ __forceinline__ void mbar_arrive(unsigned a) {
    asm volatile("mbarrier.arrive.release.cta.shared::cta.b64 _, [%0];" :: "r"(a) : "memory");
}
__device__ __forceinline__ void mbar_wait(unsigned a, unsigned ph) {
    unsigned done;
    asm volatile("{\n\t.reg .pred p;\n\t"
                 "mbarrier.try_wait.parity.acquire.cta.shared::cta.b64 p, [%1], %2;\n\t"
                 "selp.b32 %0, 1, 0, p;\n\t}"
                 : "=r"(done) : "r"(a), "r"(ph) : "memory");
    while (!done) {
        asm volatile("{\n\t.reg .pred p;\n\t"
                     "mbarrier.try_wait.parity.acquire.cta.shared::cta.b64 p, [%1], %2, 0x989680;\n\t"
                     "selp.b32 %0, 1, 0, p;\n\t}"
                     : "=r"(done) : "r"(a), "r"(ph) : "memory");
    }
}

// ---------------------------------------------------------------------------
// Warp-specialized fused kernel:
//   warps 0-3 (producers): cp.async X into a 6-slot x 8KB smem ring.
//     3 commit-groups kept in flight -> 16-24KB outstanding per block, 100%
//     load-issue duty regardless of consumer progress. mbarrier handshakes.
//   warps 4-7 (consumers): mask scan (named barrier, consumer-local), then
//     per stage: 8-token f32x2 GEMM body from smem (X LDS.32 conflict-free,
//     W label-pairs LDS.64 conflict-free), then softmax + compaction scatter.
// ---------------------------------------------------------------------------
__global__ __launch_bounds__(256, 2) void bertner_kernel(
    const float* __restrict__ X, const int* __restrict__ mask,
    const float* __restrict__ W, const float* __restrict__ bias,
    float* __restrict__ out) {

    extern __shared__ float dyns[];
    float* sX  = dyns;                         // [NST][STAGE_F] = 49152 B
    u64*   sW2 = (u64*)(dyns + NST * STAGE_F); // [HH][NLP] label pairs = 30720 B
    __shared__ u64 mb_full[NST], mb_empty[NST];
    __shared__ int sh_slot[TOKPB];
    __shared__ int sh_wsum[4];

    int tid = threadIdx.x;
    unsigned full_u  = (unsigned)__cvta_generic_to_shared(&mb_full[0]);
    unsigned empty_u = (unsigned)__cvta_generic_to_shared(&mb_empty[0]);

    if (tid == 0) {
        #pragma unroll
        for (int s = 0; s < NST; s++) {
            mbar_init(full_u  + 8u * s, 128);
            mbar_init(empty_u + 8u * s, 128);
        }
    }

    // ---- W pack (all 256 threads): sW2[k*5+p] = (W[k][2p], W[k][2p+1]) ----
    for (int idx = tid; idx < HH * NLP; idx += 256) {
        int k = idx / NLP;
        int p = idx - k * NLP;
        float lo = W[k * LL + 2 * p];
        float hi = (2 * p + 1 < LL) ? W[k * LL + 2 * p + 1] : 0.f;
        sW2[idx] = pack2(lo, hi);
    }
    __syncthreads();   // mbarriers + sW2 visible; threads now diverge by role

    int tokblk = blockIdx.x * TOKPB;
    int row    = tokblk >> 9;          // / SS
    int r0     = tokblk & (SS - 1);
    const float* xg = X + (size_t)tokblk * HH;

    if (tid < 128) {
        // ================= PRODUCER (warps 0-3) =================
        unsigned sX_u = (unsigned)__cvta_generic_to_shared(sX);
        for (int s = 0; s < NITER + 2; s++) {
            if (s < NITER) {
                int slot = s % NST;
                if (s >= NST)
                    mbar_wait(empty_u + 8u * slot, ((s - NST) / NST) & 1);
                #pragma unroll
                for (int i = 0; i < 4; i++) {
                    int c   = i * 128 + tid;       // 0..511 16B chunks
                    int tok = c >> 4;
                    int off = c & 15;
                    cp_async16(sX_u + (unsigned)((slot * STAGE_F + c * 4) * 4),
                               xg + tok * HH + s * STAGE_K + off * 4);
                }
            }
            cp_commit();                 // empty groups in the 2 tail iters
            if (s >= 2) {
                cp_wait2();              // stage s-2 fully landed (this thread)
                mbar_arrive(full_u + 8u * ((s - 2) % NST));
            }
        }
    } else {
        // ================= CONSUMER (warps 4-7) =================
        int ctid = tid - 128;
        int lane = ctid & 31;
        int cw   = ctid >> 5;           // 0..3

        // ---- per-row compaction scan (consumer threads only, int4 each) ----
        int4 m4 = ((const int4*)(mask + row * SS))[ctid];
        int msum = m4.x + m4.y + m4.z + m4.w;
        int v = msum;
        #pragma unroll
        for (int o = 1; o < 32; o <<= 1) {
            int n = __shfl_up_sync(0xffffffffu, v, o);
            if (lane >= o) v += n;
        }
        if (lane == 31) sh_wsum[cw] = v;
        asm volatile("bar.sync 1, 128;" ::: "memory");

        int wpre = 0;
        #pragma unroll
        for (int w = 0; w < 4; w++) if (w < cw) wpre += sh_wsum[w];
        int total = sh_wsum[0] + sh_wsum[1] + sh_wsum[2] + sh_wsum[3];
        int run = wpre + v - msum;

        int mm[4] = {m4.x, m4.y, m4.z, m4.w};
        #pragma unroll
        for (int c = 0; c < 4; c++) {
            int sc = 4 * ctid + c;
            int code;
            if (mm[c]) { code = run; run++; }
            else       { code = ~(total + sc - run); }
            if (sc >= r0 && sc < r0 + TOKPB) sh_slot[sc - r0] = code;
        }
        asm volatile("bar.sync 1, 128;" ::: "memory");

        // ---- pipelined GEMM: 8 tokens per warp, X from smem ring ----
        u64 acc[TPW][NLP];
        #pragma unroll
        for (int t = 0; t < TPW; t++)
            #pragma unroll
            for (int p = 0; p < NLP; p++) acc[t][p] = 0ull;

        const float* xw0 = sX + (cw * TPW) * STAGE_K;   // this warp's tokens

        for (int s = 0; s < NITER; s++) {
            int slot = s % NST;
            mbar_wait(full_u + 8u * slot, (s / NST) & 1);
            const float* xs = xw0 + slot * STAGE_F;

            #pragma unroll
            for (int u = 0; u < 2; u++) {
                int k = s * STAGE_K + u * 32 + lane;
                const u64* wp = sW2 + k * NLP;
                u64 w[NLP];
                #pragma unroll
                for (int p = 0; p < NLP; p++) w[p] = wp[p];   // LDS.64 cf

                #pragma unroll
                for (int t = 0; t < TPW; t++) {
                    float xv = xs[t * STAGE_K + u * 32 + lane]; // bank=lane, cf
                    u64 xd = dup2(xv);
                    #pragma unroll
                    for (int p = 0; p < NLP; p++) ffma2(acc[t][p], xd, w[p]);
                }
            }
            mbar_arrive(empty_u + 8u * slot);
        }

        // ---- packed butterfly reduction ----
        #pragma unroll
        for (int t = 0; t < TPW; t++)
            #pragma unroll
            for (int p = 0; p < NLP; p++)
                #pragma unroll
                for (int o = 16; o > 0; o >>= 1) {
                    u64 other = __shfl_xor_sync(0xffffffffu, acc[t][p], o);
                    acc[t][p] = fadd2(acc[t][p], other);
                }

        // ---- bias + bias-softmax precompute ----
        float bb2[LL], be[LL];
        #pragma unroll
        for (int j = 0; j < LL; j++) bb2[j] = bias[j];
        float bmx = bb2[0];
        #pragma unroll
        for (int j = 1; j < LL; j++) bmx = fmaxf(bmx, bb2[j]);
        float bsum = 0.f;
        #pragma unroll
        for (int j = 0; j < LL; j++) { be[j] = expf(bb2[j] - bmx); bsum += be[j]; }
        float binv = 1.f / bsum;

        // ---- finalize: lanes 0..7 each own one token ----
        #pragma unroll
        for (int t = 0; t < TPW; t++) {
            if (lane == t) {
                int code = sh_slot[cw * TPW + t];
                if (code >= 0) {
                    float v2[LL];
                    float mx = -1e30f;
                    #pragma unroll
                    for (int p = 0; p < NLP; p++) {
                        float lo, hi;
                        unpack2(acc[t][p], lo, hi);
                        v2[2*p] = lo + bb2[2*p];
                        mx = fmaxf(mx, v2[2*p]);
                        if (2*p + 1 < LL) {
                            v2[2*p+1] = hi + bb2[2*p+1];
                            mx = fmaxf(mx, v2[2*p+1]);
                        }
                    }
                    float ssum = 0.f;
                    #pragma unroll
                    for (int j = 0; j < LL; j++) { v2[j] = expf(v2[j] - mx); ssum += v2[j]; }
                    float inv = 1.f / ssum;
                    float* o = out + ((size_t)row * SS + code) * LL;
                    #pragma unroll
                    for (int j = 0; j < LL; j++) o[j] = v2[j] * inv;
                } else {
                    int islot = ~code;
                    float* o = out + ((size_t)row * SS + islot) * LL;
                    #pragma unroll
                    for (int j = 0; j < LL; j++) o[j] = be[j] * binv;
                }
            }
        }
    }
}

// ---------------------------------------------------------------------------
// Launch. Inputs (metadata order): sequence_output f32[64*512*768],
// valid_mask i32[64*512], W f32[768*9], b f32[9]. Output f32[64*512*9].
// ---------------------------------------------------------------------------
extern "C" void kernel_launch(void* const* d_in, const int* in_sizes, int n_in,
                              void* d_out, int out_size) {
    const float* X    = (const float*)d_in[0];
    const int*   mask = (const int*)d_in[1];
    const float* W    = (const float*)d_in[2];
    const float* bias = (const float*)d_in[3];
    float* out = (float*)d_out;

    int smem = NST * STAGE_F * 4 + HH * NLP * 8;   // 49152 + 30720 = 79872 B
    cudaFuncSetAttribute(bertner_kernel,
                         cudaFuncAttributeMaxDynamicSharedMemorySize, smem);
    bertner_kernel<<<NTOK / TOKPB, 256, smem>>>(X, mask, W, bias, out);
}

// round 15
// speedup vs baseline: 1.3574x; 1.3574x over previous
#include <cuda_runtime.h>
#include <math.h>

#define BB 64
#define SS 512
#define HH 768
#define LL 9
#define NTOK (BB*SS)
#define TPW 8              // tokens per warp
#define WPB 4              // warps per block (128 threads)
#define TOKPB (TPW*WPB)    // 32 tokens per block (one row spans 16 blocks)
#define WPAD 12            // padded W row stride (floats): conflict-free + float4-able

typedef unsigned long long u64;

__device__ __forceinline__ u64 pack2(float lo, float hi) {
    u64 r; asm("mov.b64 %0, {%1, %2};" : "=l"(r) : "f"(lo), "f"(hi)); return r;
}
__device__ __forceinline__ void unpack2(u64 v, float &lo, float &hi) {
    asm("mov.b64 {%0, %1}, %2;" : "=f"(lo), "=f"(hi) : "l"(v));
}
__device__ __forceinline__ void ffma2(u64 &d, u64 a, u64 b) {
    asm("fma.rn.f32x2 %0, %1, %2, %0;" : "+l"(d) : "l"(a), "l"(b));
}
__device__ __forceinline__ u64 fadd2(u64 a, u64 b) {
    u64 r; asm("add.rn.f32x2 %0, %1, %2;" : "=l"(r) : "l"(a), "l"(b)); return r;
}

// ---------------------------------------------------------------------------
// R2 champion kernel (35.3us), single change: k-loop unroll 4 -> 8.
// The simple load->FMA body with deep unroll is what lets ptxas software-
// pipeline loads across iterations (SASS-level MLP); every manual batching/
// prefetch/ring variant constrained that scheduler and regressed.
//   1. per-block re-scan of this row's valid_mask -> slot code per token
//   2. tall-skinny GEMM [8 tok/warp, 768] @ [768, 9], token-pair f32x2 FMAs
//   3. bias + softmax + compacting scatter (bijection; no pre-fill needed)
// ---------------------------------------------------------------------------
__global__ __launch_bounds__(128, 4) void bertner_kernel(
    const float* __restrict__ X, const int* __restrict__ mask,
    const float* __restrict__ W, const float* __restrict__ bias,
    float* __restrict__ out) {

    __shared__ float shW[HH * WPAD];
    __shared__ int   sh_slot[TOKPB];
    __shared__ int   sh_wsum[WPB];

    int tid  = threadIdx.x;
    int lane = tid & 31;
    int wid  = tid >> 5;

    // ---- cooperative W load into padded smem ----
    for (int idx = tid; idx < HH * LL; idx += 128) {
        int k = idx / LL;
        int j = idx - k * LL;
        shW[k * WPAD + j] = W[idx];
    }

    // ---- per-row compaction scan (each block redundantly scans its row) ----
    int tokblk = blockIdx.x * TOKPB;
    int row    = tokblk >> 9;          // / SS
    int r0     = tokblk & (SS - 1);    // row-local start of this block's tokens

    int4 m4 = ((const int4*)(mask + row * SS))[tid];   // tokens 4*tid .. 4*tid+3
    int msum = m4.x + m4.y + m4.z + m4.w;
    int v = msum;
    #pragma unroll
    for (int o = 1; o < 32; o <<= 1) {
        int n = __shfl_up_sync(0xffffffffu, v, o);
        if (lane >= o) v += n;
    }
    if (lane == 31) sh_wsum[wid] = v;
    __syncthreads();

    int wpre = 0;
    #pragma unroll
    for (int w = 0; w < WPB; w++) if (w < wid) wpre += sh_wsum[w];
    int total = sh_wsum[0] + sh_wsum[1] + sh_wsum[2] + sh_wsum[3];
    int run = wpre + v - msum;         // exclusive valid-prefix before token 4*tid

    int mm[4] = {m4.x, m4.y, m4.z, m4.w};
    #pragma unroll
    for (int c = 0; c < 4; c++) {
        int sc = 4 * tid + c;
        int code;
        if (mm[c]) { code = run; run++; }
        else       { code = ~(total + sc - run); }   // tail slot, encoded negative
        if (sc >= r0 && sc < r0 + TOKPB) sh_slot[sc - r0] = code;
    }
    __syncthreads();   // covers shW + sh_slot

    // ---- main GEMM: warp handles 8 tokens, lane owns k = lane + 32*i ----
    int tok0 = tokblk + wid * TPW;
    const float* xb = X + (size_t)tok0 * HH;

    u64 acc[TPW/2][LL];
    #pragma unroll
    for (int p = 0; p < TPW/2; p++)
        #pragma unroll
        for (int j = 0; j < LL; j++) acc[p][j] = 0ull;

    const float4* shW4 = (const float4*)shW;

    #pragma unroll 8
    for (int i = 0; i < HH / 32; i++) {       // 24 iterations
        int k = i * 32 + lane;
        float4 w0 = shW4[k * 3 + 0];
        float4 w1 = shW4[k * 3 + 1];
        float4 w2 = shW4[k * 3 + 2];
        float xv[TPW];
        #pragma unroll
        for (int t = 0; t < TPW; t++) xv[t] = xb[t * HH + k];
        u64 xp[TPW/2];
        #pragma unroll
        for (int p = 0; p < TPW/2; p++) xp[p] = pack2(xv[2*p], xv[2*p+1]);

        float wv[LL] = {w0.x, w0.y, w0.z, w0.w, w1.x, w1.y, w1.z, w1.w, w2.x};
        #pragma unroll
        for (int j = 0; j < LL; j++) {
            u64 wp = pack2(wv[j], wv[j]);
            #pragma unroll
            for (int p = 0; p < TPW/2; p++) ffma2(acc[p][j], xp[p], wp);
        }
    }

    // ---- packed butterfly reduction: every lane ends with full sums ----
    #pragma unroll
    for (int p = 0; p < TPW/2; p++)
        #pragma unroll
        for (int j = 0; j < LL; j++)
            #pragma unroll
            for (int o = 16; o > 0; o >>= 1) {
                u64 other = __shfl_xor_sync(0xffffffffu, acc[p][j], o);
                acc[p][j] = fadd2(acc[p][j], other);
            }

    // ---- bias + bias-softmax precompute (cheap, per thread) ----
    float bb[LL], be[LL];
    #pragma unroll
    for (int j = 0; j < LL; j++) bb[j] = bias[j];
    float bmx = bb[0];
    #pragma unroll
    for (int j = 1; j < LL; j++) bmx = fmaxf(bmx, bb[j]);
    float bsum = 0.f;
    #pragma unroll
    for (int j = 0; j < LL; j++) { be[j] = expf(bb[j] - bmx); bsum += be[j]; }
    float binv = 1.f / bsum;

    // ---- finalize: lanes 0..7 each own one token (static acc indexing) ----
    #pragma unroll
    for (int t = 0; t < TPW; t++) {
        if (lane == t) {
            int code = sh_slot[wid * TPW + t];
            if (code >= 0) {
                float v2[LL];
                float mx = -1e30f;
                #pragma unroll
                for (int j = 0; j < LL; j++) {
                    float lo, hi;
                    unpack2(acc[t >> 1][j], lo, hi);
                    v2[j] = ((t & 1) ? hi : lo) + bb[j];
                    mx = fmaxf(mx, v2[j]);
                }
                float ssum = 0.f;
                #pragma unroll
                for (int j = 0; j < LL; j++) { v2[j] = expf(v2[j] - mx); ssum += v2[j]; }
                float inv = 1.f / ssum;
                float* o = out + ((size_t)row * SS + code) * LL;
                #pragma unroll
                for (int j = 0; j < LL; j++) o[j] = v2[j] * inv;
            } else {
                int islot = ~code;
                float* o = out + ((size_t)row * SS + islot) * LL;
                #pragma unroll
                for (int j = 0; j < LL; j++) o[j] = be[j] * binv;
            }
        }
    }
}

// ---------------------------------------------------------------------------
// Launch. Inputs (metadata order): sequence_output f32[64*512*768],
// valid_mask i32[64*512], W f32[768*9], b f32[9]. Output f32[64*512*9].
// ---------------------------------------------------------------------------
extern "C" void kernel_launch(void* const* d_in, const int* in_sizes, int n_in,
                              void* d_out, int out_size) {
    const float* X    = (const float*)d_in[0];
    const int*   mask = (const int*)d_in[1];
    const float* W    = (const float*)d_in[2];
    const float* bias = (const float*)d_in[3];
    float* out = (float*)d_out;

    bertner_kernel<<<NTOK / TOKPB, 128>>>(X, mask, W, bias, out);
}